// round 6
// baseline (speedup 1.0000x reference)
#include <cuda_runtime.h>

#define BATCH 64
#define DFULL 1024
#define DIM   512
#define ODIM  1024

#define DBLK 128          // d-rows per block
#define EC   32           // e-chunk (K tile)
#define BS_STR 36         // B tile row stride (pad: bank step 4, 16B-aligned rows)
#define XS_STR 68         // x tile row stride (pad: 16B-aligned, few conflicts)
#define XD_STR 68         // epilogue x stride

// -------- scratch (device globals: no allocation allowed) --------
__device__ float g_xg[BATCH * DIM];   // normalized+gathered input
__device__ float g_y1[BATCH * DIM];   // bilinear1 output
__device__ float g_x2[BATCH * DIM];   // rms_norm(y1)
__device__ float g_y2[BATCH * DIM];   // bilinear2 output

// -------- packed f32x2 helpers (sm_103a) --------
__device__ __forceinline__ unsigned long long pack2(float lo, float hi) {
    unsigned long long r;
    asm("mov.b64 %0, {%1, %2};" : "=l"(r)
        : "r"(__float_as_uint(lo)), "r"(__float_as_uint(hi)));
    return r;
}
__device__ __forceinline__ void unpack2(unsigned long long v, float& lo, float& hi) {
    unsigned int a, b;
    asm("mov.b64 {%0, %1}, %2;" : "=r"(a), "=r"(b) : "l"(v));
    lo = __uint_as_float(a); hi = __uint_as_float(b);
}
__device__ __forceinline__ void fma2(unsigned long long& d,
                                     unsigned long long a, unsigned long long b) {
    asm("fma.rn.f32x2 %0, %1, %2, %0;" : "+l"(d) : "l"(a), "l"(b));
}
__device__ __forceinline__ float f4get(const float4& v, int j) {
    return j == 0 ? v.x : j == 1 ? v.y : j == 2 ? v.z : v.w;
}

// -------- kernel 1: L2-normalize over 1024, gather 512 cols, zero y1 --------
__global__ void norm_gather_kernel(const float* __restrict__ x,
                                   const int* __restrict__ idx) {
    const int b = blockIdx.x;
    const int t = threadIdx.x;
    float ss = 0.f;
    #pragma unroll
    for (int i = t; i < DFULL; i += 256) { float v = x[b * DFULL + i]; ss += v * v; }
    #pragma unroll
    for (int o = 16; o > 0; o >>= 1) ss += __shfl_xor_sync(0xffffffffu, ss, o);
    __shared__ float red[8];
    if ((t & 31) == 0) red[t >> 5] = ss;
    __syncthreads();
    float tot = 0.f;
    #pragma unroll
    for (int w = 0; w < 8; w++) tot += red[w];
    const float inv = rsqrtf(tot);
    #pragma unroll
    for (int j = t; j < DIM; j += 256) {
        g_xg[b * DIM + j] = x[b * DFULL + idx[j]] * inv;
        g_y1[b * DIM + j] = 0.f;
    }
}

// -------- kernel 3: L2-normalize rows of y1 -> x2, zero y2 --------
__global__ void rmsnorm_kernel() {
    const int b = blockIdx.x;
    const int t = threadIdx.x;
    float ss = 0.f;
    #pragma unroll
    for (int i = t; i < DIM; i += 256) { float v = g_y1[b * DIM + i]; ss += v * v; }
    #pragma unroll
    for (int o = 16; o > 0; o >>= 1) ss += __shfl_xor_sync(0xffffffffu, ss, o);
    __shared__ float red[8];
    if ((t & 31) == 0) red[t >> 5] = ss;
    __syncthreads();
    float tot = 0.f;
    #pragma unroll
    for (int w = 0; w < 8; w++) tot += red[w];
    const float inv = rsqrtf(tot);
    #pragma unroll
    for (int j = t; j < DIM; j += 256) {
        g_x2[b * DIM + j] = g_y1[b * DIM + j] * inv;
        g_y2[b * DIM + j] = 0.f;
    }
}

// -------- kernel 2/4: bilinear y[b,s] += sum_{d,e} B[s,d,e] x[b,d] x[b,e] --------
// grid (512 s, 4 d-blocks), 256 threads. Per-thread micro-tile: 4 d x 8 b,
// accumulated as 16 packed f32x2 (pairs over b). FFMA2-bound by design.
__global__ __launch_bounds__(256, 2)
void bilinear_kernel(const float* __restrict__ Bt, int phase) {
    const float* __restrict__ xin = phase ? g_x2 : g_xg;
    float* yout = phase ? g_y2 : g_y1;

    const int s    = blockIdx.x;
    const int dblk = blockIdx.y * DBLK;
    const int t    = threadIdx.x;
    const int tx   = t & 7;    // b-group: b in [tx*8, tx*8+8)
    const int ty   = t >> 3;   // d-group: d in [dblk+ty*4, +4)

    __shared__ __align__(16) float sm[DBLK * XD_STR];   // 8704 floats = 34 KB
    __shared__ float ysum[BATCH];

    float* Bsh = sm;                    // [DBLK][EC] stride BS_STR  (4608 fl)
    float* xsh = sm + DBLK * BS_STR;    // [EC][BATCH] stride XS_STR (2176 fl)

    if (t < BATCH) ysum[t] = 0.f;

    const float* Bsrc = Bt + (size_t)s * DIM * DIM;

    unsigned long long acc[4][4];
    #pragma unroll
    for (int i = 0; i < 4; i++)
        #pragma unroll
        for (int j = 0; j < 4; j++) acc[i][j] = 0ull;

    for (int ec = 0; ec < DIM; ec += EC) {
        __syncthreads();
        // load B tile 128x32 (vector global loads, vector smem stores)
        {
            const int el4 = (t & 7) * 4;
            const int dl0 = t >> 3;
            #pragma unroll
            for (int r = 0; r < 4; r++) {
                int dl = r * 32 + dl0;
                float4 v = *reinterpret_cast<const float4*>(
                    Bsrc + (size_t)(dblk + dl) * DIM + ec + el4);
                *reinterpret_cast<float4*>(&Bsh[dl * BS_STR + el4]) = v;
            }
        }
        // load x tile transposed: xsh[e][b]
        {
            const int el = t & 31;
            const int b0 = t >> 5;
            #pragma unroll
            for (int r = 0; r < 8; r++) {
                int bb = r * 8 + b0;
                xsh[el * XS_STR + bb] = xin[bb * DIM + ec + el];
            }
        }
        __syncthreads();

        #pragma unroll 2
        for (int e4 = 0; e4 < EC; e4 += 4) {
            float4 av[4];
            #pragma unroll
            for (int dd = 0; dd < 4; dd++)
                av[dd] = *reinterpret_cast<const float4*>(
                    &Bsh[(ty * 4 + dd) * BS_STR + e4]);
            #pragma unroll
            for (int j = 0; j < 4; j++) {
                const float* xr = &xsh[(e4 + j) * XS_STR + tx * 8];
                ulonglong2 xv0 = *reinterpret_cast<const ulonglong2*>(xr);
                ulonglong2 xv1 = *reinterpret_cast<const ulonglong2*>(xr + 4);
                #pragma unroll
                for (int dd = 0; dd < 4; dd++) {
                    float a = f4get(av[dd], j);
                    unsigned long long pa = pack2(a, a);
                    fma2(acc[dd][0], pa, xv0.x);
                    fma2(acc[dd][1], pa, xv0.y);
                    fma2(acc[dd][2], pa, xv1.x);
                    fma2(acc[dd][3], pa, xv1.y);
                }
            }
        }
    }

    // epilogue: y[b] += sum_d x[b,d] * C[d,b]; stage x[:, dblk:dblk+128] in smem
    __syncthreads();
    {
        const int dl = t & 127;
        const int b0 = t >> 7;
        #pragma unroll
        for (int r = 0; r < 32; r++) {
            int bb = r * 2 + b0;
            sm[dl * XD_STR + bb] = xin[bb * DIM + dblk + dl];
        }
    }
    __syncthreads();

    float yv[8];
    #pragma unroll
    for (int i = 0; i < 8; i++) yv[i] = 0.f;
    #pragma unroll
    for (int dd = 0; dd < 4; dd++) {
        const float* xr = &sm[(ty * 4 + dd) * XD_STR + tx * 8];
        #pragma unroll
        for (int p = 0; p < 4; p++) {
            float lo, hi;
            unpack2(acc[dd][p], lo, hi);
            yv[2 * p]     += xr[2 * p]     * lo;
            yv[2 * p + 1] += xr[2 * p + 1] * hi;
        }
    }
    #pragma unroll
    for (int bb = 0; bb < 8; bb++)
        atomicAdd(&ysum[tx * 8 + bb], yv[bb]);
    __syncthreads();
    if (t < BATCH) atomicAdd(&yout[t * DIM + s], ysum[t]);
}

// -------- kernel 5: out[b,o] = y2[b,:] . W[o,:] + bias[o] --------
__global__ void out_kernel(const float* __restrict__ W,
                           const float* __restrict__ bias,
                           float* __restrict__ out) {
    const int b = blockIdx.x;
    const int t = threadIdx.x;
    __shared__ float xrow[DIM];
    #pragma unroll
    for (int j = t; j < DIM; j += 256) xrow[j] = g_y2[b * DIM + j];
    __syncthreads();
    #pragma unroll
    for (int o = t; o < ODIM; o += 256) {
        const float4* w4 = reinterpret_cast<const float4*>(W + (size_t)o * DIM);
        float acc = 0.f;
        #pragma unroll 4
        for (int k4 = 0; k4 < DIM / 4; k4++) {
            float4 wv = __ldg(&w4[k4]);
            const float* xr = &xrow[k4 * 4];
            acc += wv.x * xr[0] + wv.y * xr[1] + wv.z * xr[2] + wv.w * xr[3];
        }
        out[b * ODIM + o] = acc + bias[o];
    }
}

extern "C" void kernel_launch(void* const* d_in, const int* in_sizes, int n_in,
                              void* d_out, int out_size) {
    (void)out_size;
    const float *x = nullptr, *B1 = nullptr, *B2 = nullptr, *W = nullptr, *bias = nullptr;
    const int* idx = nullptr;
    for (int i = 0; i < n_in; i++) {
        switch (in_sizes[i]) {
            case BATCH * DFULL:      x    = (const float*)d_in[i]; break;
            case 134217728:          if (!B1) B1 = (const float*)d_in[i];
                                     else     B2 = (const float*)d_in[i]; break;
            case ODIM * DIM:         W    = (const float*)d_in[i]; break;
            case ODIM:               bias = (const float*)d_in[i]; break;
            case DIM:                idx  = (const int*)d_in[i];   break;
            default: break;
        }
    }
    float* out = (float*)d_out;

    norm_gather_kernel<<<BATCH, 256>>>(x, idx);
    bilinear_kernel<<<dim3(DIM, 4), 256>>>(B1, 0);
    rmsnorm_kernel<<<BATCH, 256>>>();
    bilinear_kernel<<<dim3(DIM, 4), 256>>>(B2, 1);
    out_kernel<<<BATCH, 256>>>(W, bias, out);
}

// round 8
// speedup vs baseline: 2.8731x; 2.8731x over previous
#include <cuda_runtime.h>

#define BATCH 64
#define DFULL 1024
#define DIM   512
#define ODIM  1024

// ---- bilinear GEMM tiling ----
#define MT     256                 // M rows per CTA
#define KC     32                  // K per stage
#define NSTG   16                  // DIM / KC
#define NSLOT  3                   // cp.async ring slots
#define A_STR  36                  // A smem row stride (floats): a-frag conflict-free
#define X_STR  72                  // x smem row stride (floats): b-frag conflict-free
#define A_FL   (MT * A_STR)        // 9216 floats
#define X_FL   (KC * X_STR)        // 2304 floats
#define SLOT_FL (A_FL + 2 * X_FL)  // 13824 floats
#define A_BYTES (A_FL * 4)
#define X_BYTES (X_FL * 4)
#define SLOT_BYTES (SLOT_FL * 4)   // 55296
#define SMEM_DYN (NSLOT * SLOT_BYTES)  // 165888

// -------- scratch (device globals; no allocation allowed) --------
__device__ float g_xhT[DIM * BATCH];   // tf32-hi of x, transposed [e][b]
__device__ float g_xlT[DIM * BATCH];   // exact residual lo, transposed
__device__ float g_xT [DIM * BATCH];   // full x, transposed (epilogue)
__device__ float g_x2hT[DIM * BATCH];
__device__ float g_x2lT[DIM * BATCH];
__device__ float g_x2T [DIM * BATCH];
__device__ float g_part[2 * BATCH * DIM];  // per-half partial y (no atomics)

// ================= helpers =================
__device__ __forceinline__ unsigned smem_u32(const void* p) {
    unsigned a;
    asm("{ .reg .u64 t; cvta.to.shared.u64 t, %1; cvt.u32.u64 %0, t; }"
        : "=r"(a) : "l"(p));
    return a;
}
__device__ __forceinline__ void cp_async16(unsigned dst, const void* src) {
    asm volatile("cp.async.cg.shared.global [%0], [%1], 16;"
                 :: "r"(dst), "l"(src) : "memory");
}
#define CP_COMMIT() asm volatile("cp.async.commit_group;" ::: "memory")
#define CP_WAIT(N)  asm volatile("cp.async.wait_group %0;" :: "n"(N) : "memory")

// m16n8k8 tf32 HMMA, D += A*B (fp32 accumulate)
#define MMA_TF32(c, a, b0, b1) \
    asm volatile("mma.sync.aligned.m16n8k8.row.col.f32.tf32.tf32.f32 " \
        "{%0,%1,%2,%3}, {%4,%5,%6,%7}, {%8,%9}, {%0,%1,%2,%3};" \
        : "+f"((c)[0]), "+f"((c)[1]), "+f"((c)[2]), "+f"((c)[3]) \
        : "r"((a)[0]), "r"((a)[1]), "r"((a)[2]), "r"((a)[3]), \
          "r"(b0), "r"(b1))

__device__ __forceinline__ float block_sumsq_val(float v, int t) {
    float ss = v;
    #pragma unroll
    for (int o = 16; o > 0; o >>= 1) ss += __shfl_xor_sync(0xffffffffu, ss, o);
    __shared__ float red[8];
    if ((t & 31) == 0) red[t >> 5] = ss;
    __syncthreads();
    float tot = 0.f;
    #pragma unroll
    for (int w = 0; w < 8; w++) tot += red[w];
    return tot;
}
__device__ __forceinline__ void split_hi_lo(float v, float& h, float& l) {
    h = __uint_as_float(__float_as_uint(v) & 0xFFFFE000u);  // exact tf32 (13-bit trunc)
    l = v - h;                                              // exact residual
}

// ================= small kernels =================
__global__ void norm_gather_kernel(const float* __restrict__ x,
                                   const int* __restrict__ idx) {
    const int b = blockIdx.x, t = threadIdx.x;
    float ss = 0.f;
    for (int i = t; i < DFULL; i += 256) { float v = x[b * DFULL + i]; ss += v * v; }
    const float inv = rsqrtf(block_sumsq_val(ss, t));
    for (int j = t; j < DIM; j += 256) {
        float v = x[b * DFULL + idx[j]] * inv;
        float h, l; split_hi_lo(v, h, l);
        g_xhT[j * BATCH + b] = h;
        g_xlT[j * BATCH + b] = l;
        g_xT [j * BATCH + b] = v;
    }
}

__global__ void rmsnorm_kernel() {
    const int b = blockIdx.x, t = threadIdx.x;
    float ss = 0.f;
    for (int i = t; i < DIM; i += 256) {
        float v = g_part[b * DIM + i] + g_part[BATCH * DIM + b * DIM + i];
        ss += v * v;
    }
    const float inv = rsqrtf(block_sumsq_val(ss, t));
    for (int j = t; j < DIM; j += 256) {
        float v = (g_part[b * DIM + j] + g_part[BATCH * DIM + b * DIM + j]) * inv;
        float h, l; split_hi_lo(v, h, l);
        g_x2hT[j * BATCH + b] = h;
        g_x2lT[j * BATCH + b] = l;
        g_x2T [j * BATCH + b] = v;
    }
}

__global__ void out_kernel(const float* __restrict__ W,
                           const float* __restrict__ bias,
                           float* __restrict__ out) {
    const int b = blockIdx.x, t = threadIdx.x;
    const int o = blockIdx.y * 256 + t;
    __shared__ float xrow[DIM];
    for (int j = t; j < DIM; j += 256)
        xrow[j] = g_part[b * DIM + j] + g_part[BATCH * DIM + b * DIM + j];
    __syncthreads();
    const float4* w4 = reinterpret_cast<const float4*>(W + (size_t)o * DIM);
    float acc = 0.f;
    #pragma unroll 8
    for (int k4 = 0; k4 < DIM / 4; k4++) {
        float4 wv = __ldg(&w4[k4]);
        const float* xr = &xrow[k4 * 4];
        acc += wv.x * xr[0] + wv.y * xr[1] + wv.z * xr[2] + wv.w * xr[3];
    }
    out[b * ODIM + o] = acc + bias[o];
}

// ================= bilinear via mma.sync tf32 =================
__device__ __forceinline__ void copy_stage(unsigned sbase, int slot, int kc,
                                           const float* __restrict__ A,
                                           const float* __restrict__ xhT,
                                           const float* __restrict__ xlT, int t) {
    const unsigned sA = sbase + slot * SLOT_BYTES;
    #pragma unroll
    for (int j = 0; j < 8; j++) {                 // 2048 16B chunks of A
        int i = t + j * 256;
        int r = i >> 3, c = i & 7;
        cp_async16(sA + r * (A_STR * 4) + c * 16,
                   A + (size_t)r * DIM + kc * KC + c * 4);
    }
    const unsigned sX = sA + A_BYTES;
    #pragma unroll
    for (int j = 0; j < 2; j++) {                 // 512 chunks each of xh / xl
        int i = t + j * 256;
        int r = i >> 4, c = i & 15;
        cp_async16(sX + r * (X_STR * 4) + c * 16,
                   xhT + (kc * KC + r) * BATCH + c * 4);
        cp_async16(sX + X_BYTES + r * (X_STR * 4) + c * 16,
                   xlT + (kc * KC + r) * BATCH + c * 4);
    }
}

__global__ __launch_bounds__(256, 1)
void bilinear_mma_kernel(const float* __restrict__ Bt, int phase) {
    const float* __restrict__ xhT = phase ? g_x2hT : g_xhT;
    const float* __restrict__ xlT = phase ? g_x2lT : g_xlT;
    const float* __restrict__ xT  = phase ? g_x2T  : g_xT;

    extern __shared__ float smf[];
    __shared__ float ysum[BATCH];

    const unsigned sbase = smem_u32(smf);
    const int t = threadIdx.x;
    const int w = t >> 5;
    const int g = (t & 31) >> 2;     // groupID (0..7)
    const int tau = t & 3;           // threadID_in_group
    const int mt = blockIdx.x;       // 1024 CTAs
    const int s_out = mt >> 1;
    const int half = mt & 1;
    const float* Asrc = Bt + (size_t)mt * MT * DIM;

    if (t < BATCH) ysum[t] = 0.f;

    float acc[2][8][4];
    #pragma unroll
    for (int mi = 0; mi < 2; mi++)
        #pragma unroll
        for (int ni = 0; ni < 8; ni++)
            #pragma unroll
            for (int k = 0; k < 4; k++) acc[mi][ni][k] = 0.f;

    // prologue
    #pragma unroll
    for (int kc = 0; kc < NSLOT; kc++) {
        copy_stage(sbase, kc, kc, Asrc, xhT, xlT, t);
        CP_COMMIT();
    }

    for (int kc = 0; kc < NSTG; kc++) {
        const int sl = kc % NSLOT;
        if (kc < NSTG - 2)       CP_WAIT(2);
        else if (kc == NSTG - 2) CP_WAIT(1);
        else                     CP_WAIT(0);
        __syncthreads();

        const float* sA = smf + sl * SLOT_FL;
        const float* sX = sA + A_FL;

        #pragma unroll
        for (int kk = 0; kk < 4; kk++) {
            const int kb = kk * 8;
            unsigned a[2][4];
            #pragma unroll
            for (int mi = 0; mi < 2; mi++) {
                const float* ar = sA + (w * 32 + mi * 16 + g) * A_STR + kb + tau;
                a[mi][0] = __float_as_uint(ar[0]);
                a[mi][1] = __float_as_uint(ar[8 * A_STR]);
                a[mi][2] = __float_as_uint(ar[4]);
                a[mi][3] = __float_as_uint(ar[8 * A_STR + 4]);
            }
            const float* br = sX + (kb + tau) * X_STR + g;
            #pragma unroll
            for (int ni = 0; ni < 8; ni++) {
                unsigned bh0 = __float_as_uint(br[8 * ni]);
                unsigned bh1 = __float_as_uint(br[8 * ni + 4 * X_STR]);
                unsigned bl0 = __float_as_uint(br[8 * ni + X_FL]);
                unsigned bl1 = __float_as_uint(br[8 * ni + X_FL + 4 * X_STR]);
                MMA_TF32(acc[0][ni], a[0], bh0, bh1);
                MMA_TF32(acc[1][ni], a[1], bh0, bh1);
                MMA_TF32(acc[0][ni], a[0], bl0, bl1);
                MMA_TF32(acc[1][ni], a[1], bl0, bl1);
            }
        }
        __syncthreads();

        if (kc + NSLOT < NSTG) {
            copy_stage(sbase, sl, kc + NSLOT, Asrc, xhT, xlT, t);
            CP_COMMIT();
        }
    }

    // ---- epilogue: y[b] += sum_d H[d,b] * x[d,b] ----
    const int d0g = half * MT;
    float s0[8], s1[8];
    #pragma unroll
    for (int ni = 0; ni < 8; ni++) { s0[ni] = 0.f; s1[ni] = 0.f; }

    #pragma unroll
    for (int mi = 0; mi < 2; mi++) {
        const int dA = d0g + w * 32 + mi * 16 + g;
        #pragma unroll
        for (int ni = 0; ni < 8; ni++) {
            const float* xr = xT + dA * BATCH + 8 * ni + 2 * tau;
            float x00 = __ldg(xr);
            float x01 = __ldg(xr + 1);
            float x10 = __ldg(xr + 8 * BATCH);
            float x11 = __ldg(xr + 8 * BATCH + 1);
            s0[ni] += acc[mi][ni][0] * x00 + acc[mi][ni][2] * x10;
            s1[ni] += acc[mi][ni][1] * x01 + acc[mi][ni][3] * x11;
        }
    }
    // reduce over groupID lanes (stride-4 butterflies)
    #pragma unroll
    for (int o = 4; o <= 16; o <<= 1) {
        #pragma unroll
        for (int ni = 0; ni < 8; ni++) {
            s0[ni] += __shfl_xor_sync(0xffffffffu, s0[ni], o);
            s1[ni] += __shfl_xor_sync(0xffffffffu, s1[ni], o);
        }
    }
    if (g == 0) {
        #pragma unroll
        for (int ni = 0; ni < 8; ni++) {
            atomicAdd(&ysum[8 * ni + 2 * tau],     s0[ni]);
            atomicAdd(&ysum[8 * ni + 2 * tau + 1], s1[ni]);
        }
    }
    __syncthreads();
    if (t < BATCH)
        g_part[half * BATCH * DIM + t * DIM + s_out] = ysum[t];
}

// ================= launch =================
extern "C" void kernel_launch(void* const* d_in, const int* in_sizes, int n_in,
                              void* d_out, int out_size) {
    (void)out_size;
    const float *x = nullptr, *B1 = nullptr, *B2 = nullptr, *W = nullptr, *bias = nullptr;
    const int* idx = nullptr;
    for (int i = 0; i < n_in; i++) {
        switch (in_sizes[i]) {
            case BATCH * DFULL:  x = (const float*)d_in[i]; break;
            case 134217728:      if (!B1) B1 = (const float*)d_in[i];
                                 else     B2 = (const float*)d_in[i]; break;
            case ODIM * DIM:     W = (const float*)d_in[i]; break;
            case ODIM:           bias = (const float*)d_in[i]; break;
            case DIM:            idx = (const int*)d_in[i]; break;
            default: break;
        }
    }
    float* out = (float*)d_out;

    cudaFuncSetAttribute(bilinear_mma_kernel,
                         cudaFuncAttributeMaxDynamicSharedMemorySize, SMEM_DYN);

    norm_gather_kernel<<<BATCH, 256>>>(x, idx);
    bilinear_mma_kernel<<<(DIM * DIM) / MT, 256, SMEM_DYN>>>(B1, 0);
    rmsnorm_kernel<<<BATCH, 256>>>();
    bilinear_mma_kernel<<<(DIM * DIM) / MT, 256, SMEM_DYN>>>(B2, 1);
    out_kernel<<<dim3(BATCH, ODIM / 256), 256>>>(W, bias, out);
}

// round 9
// speedup vs baseline: 3.7225x; 1.2956x over previous
#include <cuda_runtime.h>

#define BATCH 64
#define DFULL 1024
#define DIM   512
#define ODIM  1024

// ---- bilinear GEMM tiling ----
#define MT     128                 // M rows per CTA
#define KC     32                  // K per stage
#define NSTG   16                  // DIM / KC
#define NSLOT  4                   // cp.async ring slots
#define A_STR  36                  // A smem row stride (floats): a-frag conflict-free
#define X_STR  72                  // x smem row stride (floats): b-frag conflict-free
#define A_FL   (MT * A_STR)        // 4608 floats
#define X_FL   (KC * X_STR)        // 2304 floats
#define SLOT_FL (A_FL + X_FL)      // 6912 floats
#define A_BYTES (A_FL * 4)         // 18432
#define SLOT_BYTES (SLOT_FL * 4)   // 27648
#define SMEM_DYN (NSLOT * SLOT_BYTES)  // 110592 -> 2 CTAs/SM

// -------- scratch (device globals; no allocation allowed) --------
__device__ float g_xhT[DIM * BATCH];   // tf32-RN x, transposed [e][b] (MMA operand)
__device__ float g_xT [DIM * BATCH];   // full x, transposed (epilogue)
__device__ float g_x2hT[DIM * BATCH];
__device__ float g_x2T [DIM * BATCH];
__device__ float g_part[4 * BATCH * DIM];  // per-quarter partial y (no gmem atomics)

// ================= helpers =================
__device__ __forceinline__ unsigned smem_u32(const void* p) {
    unsigned a;
    asm("{ .reg .u64 t; cvta.to.shared.u64 t, %1; cvt.u32.u64 %0, t; }"
        : "=r"(a) : "l"(p));
    return a;
}
__device__ __forceinline__ void cp_async16(unsigned dst, const void* src) {
    asm volatile("cp.async.cg.shared.global [%0], [%1], 16;"
                 :: "r"(dst), "l"(src) : "memory");
}
#define CP_COMMIT() asm volatile("cp.async.commit_group;" ::: "memory")
#define CP_WAIT(N)  asm volatile("cp.async.wait_group %0;" :: "n"(N) : "memory")

// m16n8k8 tf32 HMMA, D += A*B (fp32 accumulate)
#define MMA_TF32(c, a, b0, b1) \
    asm volatile("mma.sync.aligned.m16n8k8.row.col.f32.tf32.tf32.f32 " \
        "{%0,%1,%2,%3}, {%4,%5,%6,%7}, {%8,%9}, {%0,%1,%2,%3};" \
        : "+f"((c)[0]), "+f"((c)[1]), "+f"((c)[2]), "+f"((c)[3]) \
        : "r"((a)[0]), "r"((a)[1]), "r"((a)[2]), "r"((a)[3]), \
          "r"(b0), "r"(b1))

__device__ __forceinline__ float block_sumsq_val(float v, int t) {
    float ss = v;
    #pragma unroll
    for (int o = 16; o > 0; o >>= 1) ss += __shfl_xor_sync(0xffffffffu, ss, o);
    __shared__ float red[8];
    if ((t & 31) == 0) red[t >> 5] = ss;
    __syncthreads();
    float tot = 0.f;
    #pragma unroll
    for (int w = 0; w < 8; w++) tot += red[w];
    return tot;
}
__device__ __forceinline__ float tf32_rn(float v) {
    unsigned r;
    asm("cvt.rna.tf32.f32 %0, %1;" : "=r"(r) : "f"(v));
    return __uint_as_float(r);
}
__device__ __forceinline__ float part4(int b, int j) {
    return g_part[b * DIM + j]
         + g_part[1 * BATCH * DIM + b * DIM + j]
         + g_part[2 * BATCH * DIM + b * DIM + j]
         + g_part[3 * BATCH * DIM + b * DIM + j];
}

// ================= small kernels =================
__global__ void norm_gather_kernel(const float* __restrict__ x,
                                   const int* __restrict__ idx) {
    const int b = blockIdx.x, t = threadIdx.x;
    float ss = 0.f;
    for (int i = t; i < DFULL; i += 256) { float v = x[b * DFULL + i]; ss += v * v; }
    const float inv = rsqrtf(block_sumsq_val(ss, t));
    for (int j = t; j < DIM; j += 256) {
        float v = x[b * DFULL + idx[j]] * inv;
        g_xhT[j * BATCH + b] = tf32_rn(v);
        g_xT [j * BATCH + b] = v;
    }
}

__global__ void rmsnorm_kernel() {
    const int b = blockIdx.x, t = threadIdx.x;
    float ss = 0.f;
    for (int i = t; i < DIM; i += 256) { float v = part4(b, i); ss += v * v; }
    const float inv = rsqrtf(block_sumsq_val(ss, t));
    for (int j = t; j < DIM; j += 256) {
        float v = part4(b, j) * inv;
        g_x2hT[j * BATCH + b] = tf32_rn(v);
        g_x2T [j * BATCH + b] = v;
    }
}

__global__ void out_kernel(const float* __restrict__ W,
                           const float* __restrict__ bias,
                           float* __restrict__ out) {
    const int b = blockIdx.x, t = threadIdx.x;
    const int o = blockIdx.y * 256 + t;
    __shared__ float xrow[DIM];
    for (int j = t; j < DIM; j += 256) xrow[j] = part4(b, j);
    __syncthreads();
    const float4* w4 = reinterpret_cast<const float4*>(W + (size_t)o * DIM);
    float acc = 0.f;
    #pragma unroll 8
    for (int k4 = 0; k4 < DIM / 4; k4++) {
        float4 wv = __ldg(&w4[k4]);
        const float* xr = &xrow[k4 * 4];
        acc += wv.x * xr[0] + wv.y * xr[1] + wv.z * xr[2] + wv.w * xr[3];
    }
    out[b * ODIM + o] = acc + bias[o];
}

// ================= bilinear via mma.sync tf32 =================
__device__ __forceinline__ void copy_stage(unsigned sbase, int slot, int kc,
                                           const float* __restrict__ A,
                                           const float* __restrict__ xhT, int t) {
    const unsigned sA = sbase + slot * SLOT_BYTES;
    #pragma unroll
    for (int j = 0; j < 4; j++) {                 // 1024 16B chunks of A (128x32 fp32)
        int i = t + j * 256;
        int r = i >> 3, c = i & 7;
        cp_async16(sA + r * (A_STR * 4) + c * 16,
                   A + (size_t)r * DIM + kc * KC + c * 4);
    }
    const unsigned sX = sA + A_BYTES;
    {                                             // 512 chunks of x (32x64 fp32)
        #pragma unroll
        for (int j = 0; j < 2; j++) {
            int i = t + j * 256;
            int r = i >> 4, c = i & 15;
            cp_async16(sX + r * (X_STR * 4) + c * 16,
                       xhT + (kc * KC + r) * BATCH + c * 4);
        }
    }
}

__global__ __launch_bounds__(256, 2)
void bilinear_mma_kernel(const float* __restrict__ Bt, int phase) {
    const float* __restrict__ xhT = phase ? g_x2hT : g_xhT;
    const float* __restrict__ xT  = phase ? g_x2T  : g_xT;

    extern __shared__ float smf[];
    __shared__ float ysum[BATCH];

    const unsigned sbase = smem_u32(smf);
    const int t = threadIdx.x;
    const int w = t >> 5;
    const int g = (t & 31) >> 2;     // groupID (0..7)
    const int tau = t & 3;           // threadID_in_group
    const int mt = blockIdx.x;       // 2048 CTAs
    const int s_out = mt >> 2;
    const int quarter = mt & 3;
    const float* Asrc = Bt + (size_t)mt * MT * DIM;

    if (t < BATCH) ysum[t] = 0.f;

    float acc[8][4];
    #pragma unroll
    for (int ni = 0; ni < 8; ni++)
        #pragma unroll
        for (int k = 0; k < 4; k++) acc[ni][k] = 0.f;

    // prologue: fill the ring
    #pragma unroll
    for (int kc = 0; kc < NSLOT; kc++) {
        copy_stage(sbase, kc, kc, Asrc, xhT, t);
        CP_COMMIT();
    }

    for (int kc = 0; kc < NSTG; kc++) {
        const int sl = kc & (NSLOT - 1);
        if (kc <= NSTG - NSLOT)       CP_WAIT(3);
        else if (kc == NSTG - 3)      CP_WAIT(2);
        else if (kc == NSTG - 2)      CP_WAIT(1);
        else                          CP_WAIT(0);
        __syncthreads();

        const float* sA = smf + sl * SLOT_FL;
        const float* sX = sA + A_FL;

        #pragma unroll
        for (int kk = 0; kk < 4; kk++) {
            const int kb = kk * 8;
            unsigned a[4];
            const float* ar = sA + (w * 16 + g) * A_STR + kb + tau;
            a[0] = __float_as_uint(ar[0]);
            a[1] = __float_as_uint(ar[8 * A_STR]);
            a[2] = __float_as_uint(ar[4]);
            a[3] = __float_as_uint(ar[8 * A_STR + 4]);
            const float* br = sX + (kb + tau) * X_STR + g;
            #pragma unroll
            for (int ni = 0; ni < 8; ni++) {
                unsigned b0 = __float_as_uint(br[8 * ni]);
                unsigned b1 = __float_as_uint(br[8 * ni + 4 * X_STR]);
                MMA_TF32(acc[ni], a, b0, b1);
            }
        }
        __syncthreads();

        if (kc + NSLOT < NSTG) {
            copy_stage(sbase, sl, kc + NSLOT, Asrc, xhT, t);
            CP_COMMIT();
        }
    }

    // ---- epilogue: y[b] += sum_d H[d,b] * x[d,b] ----
    const int dA = quarter * MT + w * 16 + g;
    float s0[8], s1[8];
    #pragma unroll
    for (int ni = 0; ni < 8; ni++) { s0[ni] = 0.f; s1[ni] = 0.f; }

    #pragma unroll
    for (int ni = 0; ni < 8; ni++) {
        const float* xr = xT + dA * BATCH + 8 * ni + 2 * tau;
        float x00 = __ldg(xr);
        float x01 = __ldg(xr + 1);
        float x10 = __ldg(xr + 8 * BATCH);
        float x11 = __ldg(xr + 8 * BATCH + 1);
        s0[ni] += acc[ni][0] * x00 + acc[ni][2] * x10;
        s1[ni] += acc[ni][1] * x01 + acc[ni][3] * x11;
    }
    // reduce over groupID lanes (stride-4 butterflies)
    #pragma unroll
    for (int o = 4; o <= 16; o <<= 1) {
        #pragma unroll
        for (int ni = 0; ni < 8; ni++) {
            s0[ni] += __shfl_xor_sync(0xffffffffu, s0[ni], o);
            s1[ni] += __shfl_xor_sync(0xffffffffu, s1[ni], o);
        }
    }
    if (g == 0) {
        #pragma unroll
        for (int ni = 0; ni < 8; ni++) {
            atomicAdd(&ysum[8 * ni + 2 * tau],     s0[ni]);
            atomicAdd(&ysum[8 * ni + 2 * tau + 1], s1[ni]);
        }
    }
    __syncthreads();
    if (t < BATCH)
        g_part[quarter * BATCH * DIM + t * DIM + s_out] = ysum[t];
}

// ================= launch =================
extern "C" void kernel_launch(void* const* d_in, const int* in_sizes, int n_in,
                              void* d_out, int out_size) {
    (void)out_size;
    const float *x = nullptr, *B1 = nullptr, *B2 = nullptr, *W = nullptr, *bias = nullptr;
    const int* idx = nullptr;
    for (int i = 0; i < n_in; i++) {
        switch (in_sizes[i]) {
            case BATCH * DFULL:  x = (const float*)d_in[i]; break;
            case 134217728:      if (!B1) B1 = (const float*)d_in[i];
                                 else     B2 = (const float*)d_in[i]; break;
            case ODIM * DIM:     W = (const float*)d_in[i]; break;
            case ODIM:           bias = (const float*)d_in[i]; break;
            case DIM:            idx = (const int*)d_in[i]; break;
            default: break;
        }
    }
    float* out = (float*)d_out;

    cudaFuncSetAttribute(bilinear_mma_kernel,
                         cudaFuncAttributeMaxDynamicSharedMemorySize, SMEM_DYN);

    norm_gather_kernel<<<BATCH, 256>>>(x, idx);
    bilinear_mma_kernel<<<(DIM * DIM) / MT, 256, SMEM_DYN>>>(B1, 0);
    rmsnorm_kernel<<<BATCH, 256>>>();
    bilinear_mma_kernel<<<(DIM * DIM) / MT, 256, SMEM_DYN>>>(B2, 1);
    out_kernel<<<dim3(BATCH, ODIM / 256), 256>>>(W, bias, out);
}

// round 10
// speedup vs baseline: 3.7361x; 1.0037x over previous
#include <cuda_runtime.h>

#define BATCH 64
#define DFULL 1024
#define DIM   512
#define ODIM  1024

// ---- bilinear GEMM tiling ----
#define MT     128                 // M rows per CTA
#define KC     32                  // K per stage
#define NSTG   16                  // DIM / KC
#define NSLOT  4                   // cp.async ring slots
#define A_STR  36                  // A smem row stride (floats): a-frag conflict-free
#define X_STR  72                  // x smem row stride (floats): b-frag conflict-free
#define A_FL   (MT * A_STR)        // 4608 floats
#define X_FL   (KC * X_STR)        // 2304 floats
#define SLOT_FL (A_FL + X_FL)      // 6912 floats
#define A_BYTES (A_FL * 4)         // 18432
#define SLOT_BYTES (SLOT_FL * 4)   // 27648
#define SMEM_DYN (NSLOT * SLOT_BYTES)  // 110592 -> 2 CTAs/SM

// -------- scratch (device globals; no allocation allowed) --------
__device__ float g_xhT[DIM * BATCH];   // tf32-RN x, transposed [e][b] (MMA operand)
__device__ float g_xT [DIM * BATCH];   // full x, transposed (epilogue)
__device__ float g_x2hT[DIM * BATCH];
__device__ float g_x2T [DIM * BATCH];
__device__ float g_part[4 * BATCH * DIM];  // per-quarter partial y (no gmem atomics)

// ================= helpers =================
__device__ __forceinline__ unsigned smem_u32(const void* p) {
    unsigned a;
    asm("{ .reg .u64 t; cvta.to.shared.u64 t, %1; cvt.u32.u64 %0, t; }"
        : "=r"(a) : "l"(p));
    return a;
}
__device__ __forceinline__ void cp_async16(unsigned dst, const void* src) {
    asm volatile("cp.async.cg.shared.global [%0], [%1], 16;"
                 :: "r"(dst), "l"(src) : "memory");
}
#define CP_COMMIT() asm volatile("cp.async.commit_group;" ::: "memory")
#define CP_WAIT(N)  asm volatile("cp.async.wait_group %0;" :: "n"(N) : "memory")

// m16n8k8 tf32 HMMA, D += A*B (fp32 accumulate)
#define MMA_TF32(c, a, b0, b1) \
    asm volatile("mma.sync.aligned.m16n8k8.row.col.f32.tf32.tf32.f32 " \
        "{%0,%1,%2,%3}, {%4,%5,%6,%7}, {%8,%9}, {%0,%1,%2,%3};" \
        : "+f"((c)[0]), "+f"((c)[1]), "+f"((c)[2]), "+f"((c)[3]) \
        : "r"((a)[0]), "r"((a)[1]), "r"((a)[2]), "r"((a)[3]), \
          "r"(b0), "r"(b1))

__device__ __forceinline__ float block_sumsq_val(float v, int t) {
    float ss = v;
    #pragma unroll
    for (int o = 16; o > 0; o >>= 1) ss += __shfl_xor_sync(0xffffffffu, ss, o);
    __shared__ float red[8];
    if ((t & 31) == 0) red[t >> 5] = ss;
    __syncthreads();
    float tot = 0.f;
    #pragma unroll
    for (int w = 0; w < 8; w++) tot += red[w];
    return tot;
}
__device__ __forceinline__ float tf32_rn(float v) {
    unsigned r;
    asm("cvt.rna.tf32.f32 %0, %1;" : "=r"(r) : "f"(v));
    return __uint_as_float(r);
}
__device__ __forceinline__ float part4(int b, int j) {
    return g_part[b * DIM + j]
         + g_part[1 * BATCH * DIM + b * DIM + j]
         + g_part[2 * BATCH * DIM + b * DIM + j]
         + g_part[3 * BATCH * DIM + b * DIM + j];
}

// ================= small kernels =================
__global__ void norm_gather_kernel(const float* __restrict__ x,
                                   const int* __restrict__ idx) {
    const int b = blockIdx.x, t = threadIdx.x;
    float ss = 0.f;
    for (int i = t; i < DFULL; i += 256) { float v = x[b * DFULL + i]; ss += v * v; }
    const float inv = rsqrtf(block_sumsq_val(ss, t));
    for (int j = t; j < DIM; j += 256) {
        float v = x[b * DFULL + idx[j]] * inv;
        g_xhT[j * BATCH + b] = tf32_rn(v);
        g_xT [j * BATCH + b] = v;
    }
}

__global__ void rmsnorm_kernel() {
    const int b = blockIdx.x, t = threadIdx.x;
    float ss = 0.f;
    for (int i = t; i < DIM; i += 256) { float v = part4(b, i); ss += v * v; }
    const float inv = rsqrtf(block_sumsq_val(ss, t));
    for (int j = t; j < DIM; j += 256) {
        float v = part4(b, j) * inv;
        g_x2hT[j * BATCH + b] = tf32_rn(v);
        g_x2T [j * BATCH + b] = v;
    }
}

__global__ void out_kernel(const float* __restrict__ W,
                           const float* __restrict__ bias,
                           float* __restrict__ out) {
    const int b = blockIdx.x, t = threadIdx.x;
    const int o = blockIdx.y * 256 + t;
    __shared__ float xrow[DIM];
    for (int j = t; j < DIM; j += 256) xrow[j] = part4(b, j);
    __syncthreads();
    const float4* w4 = reinterpret_cast<const float4*>(W + (size_t)o * DIM);
    float acc = 0.f;
    #pragma unroll 8
    for (int k4 = 0; k4 < DIM / 4; k4++) {
        float4 wv = __ldg(&w4[k4]);
        const float* xr = &xrow[k4 * 4];
        acc += wv.x * xr[0] + wv.y * xr[1] + wv.z * xr[2] + wv.w * xr[3];
    }
    out[b * ODIM + o] = acc + bias[o];
}

// ================= bilinear via mma.sync tf32 =================
__device__ __forceinline__ void copy_stage(unsigned sbase, int slot, int kc,
                                           const float* __restrict__ A,
                                           const float* __restrict__ xhT, int t) {
    const unsigned sA = sbase + slot * SLOT_BYTES;
    #pragma unroll
    for (int j = 0; j < 4; j++) {                 // 1024 16B chunks of A (128x32 fp32)
        int i = t + j * 256;
        int r = i >> 3, c = i & 7;
        cp_async16(sA + r * (A_STR * 4) + c * 16,
                   A + (size_t)r * DIM + kc * KC + c * 4);
    }
    const unsigned sX = sA + A_BYTES;
    {                                             // 512 chunks of x (32x64 fp32)
        #pragma unroll
        for (int j = 0; j < 2; j++) {
            int i = t + j * 256;
            int r = i >> 4, c = i & 15;
            cp_async16(sX + r * (X_STR * 4) + c * 16,
                       xhT + (kc * KC + r) * BATCH + c * 4);
        }
    }
}

__global__ __launch_bounds__(256, 2)
void bilinear_mma_kernel(const float* __restrict__ Bt, int phase) {
    const float* __restrict__ xhT = phase ? g_x2hT : g_xhT;
    const float* __restrict__ xT  = phase ? g_x2T  : g_xT;

    extern __shared__ float smf[];
    __shared__ float ysum[BATCH];

    const unsigned sbase = smem_u32(smf);
    const int t = threadIdx.x;
    const int w = t >> 5;
    const int g = (t & 31) >> 2;     // groupID (0..7)
    const int tau = t & 3;           // threadID_in_group
    const int mt = blockIdx.x;       // 2048 CTAs
    const int s_out = mt >> 2;
    const int quarter = mt & 3;
    const float* Asrc = Bt + (size_t)mt * MT * DIM;

    if (t < BATCH) ysum[t] = 0.f;

    float acc[8][4];
    #pragma unroll
    for (int ni = 0; ni < 8; ni++)
        #pragma unroll
        for (int k = 0; k < 4; k++) acc[ni][k] = 0.f;

    // prologue: fill the ring
    #pragma unroll
    for (int kc = 0; kc < NSLOT; kc++) {
        copy_stage(sbase, kc, kc, Asrc, xhT, t);
        CP_COMMIT();
    }

    for (int kc = 0; kc < NSTG; kc++) {
        const int sl = kc & (NSLOT - 1);
        if (kc <= NSTG - NSLOT)       CP_WAIT(3);
        else if (kc == NSTG - 3)      CP_WAIT(2);
        else if (kc == NSTG - 2)      CP_WAIT(1);
        else                          CP_WAIT(0);
        __syncthreads();

        const float* sA = smf + sl * SLOT_FL;
        const float* sX = sA + A_FL;

        #pragma unroll
        for (int kk = 0; kk < 4; kk++) {
            const int kb = kk * 8;
            unsigned a[4];
            const float* ar = sA + (w * 16 + g) * A_STR + kb + tau;
            a[0] = __float_as_uint(ar[0]);
            a[1] = __float_as_uint(ar[8 * A_STR]);
            a[2] = __float_as_uint(ar[4]);
            a[3] = __float_as_uint(ar[8 * A_STR + 4]);
            const float* br = sX + (kb + tau) * X_STR + g;
            #pragma unroll
            for (int ni = 0; ni < 8; ni++) {
                unsigned b0 = __float_as_uint(br[8 * ni]);
                unsigned b1 = __float_as_uint(br[8 * ni + 4 * X_STR]);
                MMA_TF32(acc[ni], a, b0, b1);
            }
        }
        __syncthreads();

        if (kc + NSLOT < NSTG) {
            copy_stage(sbase, sl, kc + NSLOT, Asrc, xhT, t);
            CP_COMMIT();
        }
    }

    // ---- epilogue: y[b] += sum_d H[d,b] * x[d,b] ----
    const int dA = quarter * MT + w * 16 + g;
    float s0[8], s1[8];
    #pragma unroll
    for (int ni = 0; ni < 8; ni++) { s0[ni] = 0.f; s1[ni] = 0.f; }

    #pragma unroll
    for (int ni = 0; ni < 8; ni++) {
        const float* xr = xT + dA * BATCH + 8 * ni + 2 * tau;
        float x00 = __ldg(xr);
        float x01 = __ldg(xr + 1);
        float x10 = __ldg(xr + 8 * BATCH);
        float x11 = __ldg(xr + 8 * BATCH + 1);
        s0[ni] += acc[ni][0] * x00 + acc[ni][2] * x10;
        s1[ni] += acc[ni][1] * x01 + acc[ni][3] * x11;
    }
    // reduce over groupID lanes (stride-4 butterflies)
    #pragma unroll
    for (int o = 4; o <= 16; o <<= 1) {
        #pragma unroll
        for (int ni = 0; ni < 8; ni++) {
            s0[ni] += __shfl_xor_sync(0xffffffffu, s0[ni], o);
            s1[ni] += __shfl_xor_sync(0xffffffffu, s1[ni], o);
        }
    }
    if (g == 0) {
        #pragma unroll
        for (int ni = 0; ni < 8; ni++) {
            atomicAdd(&ysum[8 * ni + 2 * tau],     s0[ni]);
            atomicAdd(&ysum[8 * ni + 2 * tau + 1], s1[ni]);
        }
    }
    __syncthreads();
    if (t < BATCH)
        g_part[quarter * BATCH * DIM + t * DIM + s_out] = ysum[t];
}

// ================= launch =================
extern "C" void kernel_launch(void* const* d_in, const int* in_sizes, int n_in,
                              void* d_out, int out_size) {
    (void)out_size;
    const float *x = nullptr, *B1 = nullptr, *B2 = nullptr, *W = nullptr, *bias = nullptr;
    const int* idx = nullptr;
    for (int i = 0; i < n_in; i++) {
        switch (in_sizes[i]) {
            case BATCH * DFULL:  x = (const float*)d_in[i]; break;
            case 134217728:      if (!B1) B1 = (const float*)d_in[i];
                                 else     B2 = (const float*)d_in[i]; break;
            case ODIM * DIM:     W = (const float*)d_in[i]; break;
            case ODIM:           bias = (const float*)d_in[i]; break;
            case DIM:            idx = (const int*)d_in[i]; break;
            default: break;
        }
    }
    float* out = (float*)d_out;

    cudaFuncSetAttribute(bilinear_mma_kernel,
                         cudaFuncAttributeMaxDynamicSharedMemorySize, SMEM_DYN);

    norm_gather_kernel<<<BATCH, 256>>>(x, idx);
    bilinear_mma_kernel<<<(DIM * DIM) / MT, 256, SMEM_DYN>>>(B1, 0);
    rmsnorm_kernel<<<BATCH, 256>>>();
    bilinear_mma_kernel<<<(DIM * DIM) / MT, 256, SMEM_DYN>>>(B2, 1);
    out_kernel<<<dim3(BATCH, ODIM / 256), 256>>>(W, bias, out);
}